// round 15
// baseline (speedup 1.0000x reference)
#include <cuda_runtime.h>
#include <cstdint>

#define Bv 4
#define Nv 512
#define Dv 256
#define Lv 64

typedef unsigned long long ull;

// w-folded projection, layout [b][l][n]  (512 KB)
__device__ float g_xh[Bv * Lv * Nv];
// device barrier (replay-safe: count resets, release monotone)
__device__ unsigned g_count = 0, g_release = 0;

__device__ __forceinline__ ull pk2(float a) {
    ull r;
    asm("mov.b64 %0, {%1, %2};" : "=l"(r) : "f"(a), "f"(a));
    return r;
}
__device__ __forceinline__ ull add2(ull a, ull b) {
    ull r;
    asm("add.rn.f32x2 %0, %1, %2;" : "=l"(r) : "l"(a), "l"(b));
    return r;
}
__device__ __forceinline__ float lo2(ull a) {
    float x, y;
    asm("mov.b64 {%0, %1}, %2;" : "=f"(x), "=f"(y) : "l"(a));
    return x;
}
__device__ __forceinline__ float hi2(ull a) {
    float x, y;
    asm("mov.b64 {%0, %1}, %2;" : "=f"(x), "=f"(y) : "l"(a));
    return y;
}

// ---------------------------------------------------------------------------
// Grid 128 = (b, 16-row tile), 512 threads (16 warps) -> 128 regs/thread.
// Full-work mainloop: warp w: rows rg*4..rg*4+3 (rg=w&3), j-quarter jq=w>>2,
// full l=0..63 (no l-split, no psum merge). Single grid barrier.
// Smem floats:
//   sj  [0,     32768)  [64][512]   (phase-A overlay: Wl[64][256] at 0)
//   si2 [32768, 34816)  [64][16] ull {-wv,-wv}
//   adjs[34816, 43008)  [16][512]
//   red [43008, 43072)  [16][4]
//   xs  [43072, 47232)  [16][260]  (phase A only)
// ---------------------------------------------------------------------------
__global__ __launch_bounds__(512, 1) void fused_kernel(
    const float* __restrict__ x, const float* __restrict__ adj,
    const float* __restrict__ W, const float* __restrict__ lw,
    float* __restrict__ out) {
    extern __shared__ float sm[];
    float* sj   = sm;
    ull*   si2  = (ull*)(sm + 32768);
    float* adjs = sm + 34816;
    float* red  = sm + 43008;
    float* xs   = sm + 43072;
    float* Wl   = sm;                 // phase A overlay

    int bid = blockIdx.x;
    int b = bid >> 5, i0 = (bid & 31) << 4;
    int tid = threadIdx.x;

    // ---- adj tile prefetch (independent of everything) ---------------------
    {
        const float4* asrc = (const float4*)(adj + (size_t)(b * Nv + i0) * Nv);
        float4* adst = (float4*)adjs;
#pragma unroll
        for (int k = 0; k < 4; ++k)
            adst[tid + k * 512] = asrc[tid + k * 512];
    }

    // ---- Phase A staging ----------------------------------------------------
    {
        int r = tid >> 5, d4 = tid & 31;           // 512 = 16*32, 2 float4 each
        *(float4*)&xs[r * 260 + d4 * 8] =
            *(const float4*)&x[(size_t)(b * Nv + i0 + r) * Dv + d4 * 8];
        *(float4*)&xs[r * 260 + d4 * 8 + 4] =
            *(const float4*)&x[(size_t)(b * Nv + i0 + r) * Dv + d4 * 8 + 4];
    }
#pragma unroll
    for (int k = 0; k < 8; ++k)
        ((float4*)Wl)[tid + k * 512] = ((const float4*)W)[tid + k * 512];
    __syncthreads();

    // ---- Phase A compute: two (r,l) outputs per thread ----------------------
    {
        int r = tid & 15, l0 = tid >> 4;           // l0 in 0..31; also l0+32
        const float* xp  = xs + r * 260;
        const float* wp0 = Wl + l0 * 256;
        const float* wp1 = Wl + (l0 + 32) * 256;
        float a00 = 0.f, a01 = 0.f, a10 = 0.f, a11 = 0.f;
#pragma unroll 8
        for (int d4 = 0; d4 < 64; ++d4) {
            float4 xv = *(const float4*)&xp[d4 * 4];
            float4 w0 = *(const float4*)&wp0[d4 * 4];
            float4 w1 = *(const float4*)&wp1[d4 * 4];
            a00 = fmaf(xv.x, w0.x, a00);
            a01 = fmaf(xv.y, w0.y, a01);
            a00 = fmaf(xv.z, w0.z, a00);
            a01 = fmaf(xv.w, w0.w, a01);
            a10 = fmaf(xv.x, w1.x, a10);
            a11 = fmaf(xv.y, w1.y, a11);
            a10 = fmaf(xv.z, w1.z, a10);
            a11 = fmaf(xv.w, w1.w, a11);
        }
        float v0 = (a00 + a01) * lw[l0];
        float v1 = (a10 + a11) * lw[l0 + 32];
        g_xh[b * (Lv * Nv) + l0 * Nv + i0 + r]        = v0;
        g_xh[b * (Lv * Nv) + (l0 + 32) * Nv + i0 + r] = v1;
        si2[l0 * 16 + r]        = pk2(-v0);
        si2[(l0 + 32) * 16 + r] = pk2(-v1);
    }

    // ---- Device-wide barrier ------------------------------------------------
    __syncthreads();
    if (tid == 0) {
        __threadfence();
        unsigned snap = *(volatile unsigned*)&g_release;
        unsigned old  = atomicAdd(&g_count, 1);
        if (old == 127u) {
            g_count = 0;
            __threadfence();
            atomicAdd(&g_release, 1);
        } else {
            while (*(volatile unsigned*)&g_release == snap) __nanosleep(32);
        }
        __threadfence();
    }
    __syncthreads();

    // ---- stage sj (overwrites Wl, dead) -------------------------------------
    const float* xh = g_xh + b * (Lv * Nv);
#pragma unroll
    for (int k = 0; k < 16; ++k)
        ((float4*)sj)[tid + k * 512] = ((const float4*)xh)[tid + k * 512];
    __syncthreads();

    // ---- mainloop: 4 rows x 4 j x FULL 64 l per warp ------------------------
    int w    = tid >> 5;
    int lane = tid & 31;
    int rg = w & 3;
    int jq = w >> 2;
    int jbase = jq * 128 + lane * 4;

    const ull ABS2 = 0x7FFFFFFF7FFFFFFFull;
    ull a00 = 0, a01 = 0, a10 = 0, a11 = 0;
    ull a20 = 0, a21 = 0, a30 = 0, a31 = 0;

    const float* sjp = sj + jbase;
    const ull*   sip = si2 + rg * 4;

#pragma unroll 16
    for (int l = 0; l < 64; ++l) {
        ulonglong2 j01 = *(const ulonglong2*)(sjp + (size_t)l * Nv);
        ulonglong2 nab = *(const ulonglong2*)(sip + l * 16);
        ulonglong2 ncd = *(const ulonglong2*)(sip + l * 16 + 2);
        a00 = add2(a00, add2(j01.x, nab.x) & ABS2);
        a01 = add2(a01, add2(j01.y, nab.x) & ABS2);
        a10 = add2(a10, add2(j01.x, nab.y) & ABS2);
        a11 = add2(a11, add2(j01.y, nab.y) & ABS2);
        a20 = add2(a20, add2(j01.x, ncd.x) & ABS2);
        a21 = add2(a21, add2(j01.y, ncd.x) & ABS2);
        a30 = add2(a30, add2(j01.x, ncd.y) & ABS2);
        a31 = add2(a31, add2(j01.y, ncd.y) & ABS2);
    }

    float d[4][4];
    d[0][0] = lo2(a00); d[0][1] = hi2(a00); d[0][2] = lo2(a01); d[0][3] = hi2(a01);
    d[1][0] = lo2(a10); d[1][1] = hi2(a10); d[1][2] = lo2(a11); d[1][3] = hi2(a11);
    d[2][0] = lo2(a20); d[2][1] = hi2(a20); d[2][2] = lo2(a21); d[2][3] = hi2(a21);
    d[3][0] = lo2(a30); d[3][1] = hi2(a30); d[3][2] = lo2(a31); d[3][3] = hi2(a31);

    // ---- epilogue: leaky + adj*exp + partial row sums (warp-local) ----------
    float e[4][4];
    float srow[4];
#pragma unroll
    for (int r = 0; r < 4; ++r) {
        int row = rg * 4 + r;
        const float* arow = adjs + row * Nv + jbase;
        float4 A = *(const float4*)arow;
        float v, s;
        v = d[r][0]; v = v > 0.f ? v : 0.01f * v; e[r][0] = A.x * __expf(v);
        v = d[r][1]; v = v > 0.f ? v : 0.01f * v; e[r][1] = A.y * __expf(v);
        v = d[r][2]; v = v > 0.f ? v : 0.01f * v; e[r][2] = A.z * __expf(v);
        v = d[r][3]; v = v > 0.f ? v : 0.01f * v; e[r][3] = A.w * __expf(v);
        s = e[r][0] + e[r][1] + e[r][2] + e[r][3];
#pragma unroll
        for (int o = 16; o; o >>= 1)
            s += __shfl_xor_sync(0xffffffffu, s, o);
        srow[r] = s;
    }
    if (lane == 0) {
#pragma unroll
        for (int r = 0; r < 4; ++r)
            red[(rg * 4 + r) * 4 + jq] = srow[r];
    }
    __syncthreads();

    // ---- normalize + store --------------------------------------------------
#pragma unroll
    for (int r = 0; r < 4; ++r) {
        int row = rg * 4 + r;
        float4 s4 = *(const float4*)&red[row * 4];
        float rs = 1.0f / (s4.x + s4.y + s4.z + s4.w);
        float4 o4;
        o4.x = e[r][0] * rs + 1e-10f;
        o4.y = e[r][1] * rs + 1e-10f;
        o4.z = e[r][2] * rs + 1e-10f;
        o4.w = e[r][3] * rs + 1e-10f;
        *(float4*)&out[(size_t)(b * Nv + i0 + row) * Nv + jbase] = o4;
    }
}

extern "C" void kernel_launch(void* const* d_in, const int* in_sizes, int n_in,
                              void* d_out, int out_size) {
    (void)in_sizes; (void)n_in; (void)out_size;
    const float* x   = (const float*)d_in[0];
    const float* adj = (const float*)d_in[1];
    const float* W   = (const float*)d_in[2];
    const float* lw  = (const float*)d_in[3];
    float* out = (float*)d_out;

    const int smem = 47232 * 4;   // 188928 B
    cudaFuncSetAttribute(fused_kernel,
                         cudaFuncAttributeMaxDynamicSharedMemorySize, smem);
    cudaFuncSetAttribute(fused_kernel,
                         cudaFuncAttributePreferredSharedMemoryCarveout,
                         cudaSharedmemCarveoutMaxShared);

    fused_kernel<<<Bv * 32, 512, smem>>>(x, adj, W, lw, out);
}

// round 16
// speedup vs baseline: 1.3152x; 1.3152x over previous
#include <cuda_runtime.h>
#include <cstdint>

#define Bv 4
#define Nv 512
#define Dv 256
#define Lv 64

typedef unsigned long long ull;

// w-folded projection, layout [b][l][n]  (512 KB)
__device__ float g_xh[Bv * Lv * Nv];
// device barrier (replay-safe: count resets, release monotone)
__device__ unsigned g_count = 0, g_release = 0;

__device__ __forceinline__ ull pk2(float a) {
    ull r;
    asm("mov.b64 %0, {%1, %2};" : "=l"(r) : "f"(a), "f"(a));
    return r;
}
__device__ __forceinline__ ull add2(ull a, ull b) {
    ull r;
    asm("add.rn.f32x2 %0, %1, %2;" : "=l"(r) : "l"(a), "l"(b));
    return r;
}
__device__ __forceinline__ float lo2(ull a) {
    float x, y;
    asm("mov.b64 {%0, %1}, %2;" : "=f"(x), "=f"(y) : "l"(a));
    return x;
}
__device__ __forceinline__ float hi2(ull a) {
    float x, y;
    asm("mov.b64 {%0, %1}, %2;" : "=f"(x), "=f"(y) : "l"(a));
    return y;
}

// ---------------------------------------------------------------------------
// Grid 128 = (b, 16-row tile), 1024 threads (32 warps, 8/SMSP).
// Mainloop: warp w -> rows {2rg, 2rg+1} (rg=w&7), j-quarter jq=w>>3,
// FULL l=0..63. Only 8 ull accumulators -> register slack for load-ahead.
// No psum merge phase. Single grid barrier. Parallel phase A (1 out/thread).
// Smem floats:
//   sj  [0,     32768)  [64][512]   (phase-A overlay: Wl[64][256] at 0)
//   si2 [32768, 34816)  [64][16] ull {-wv,-wv}
//   adjs[34816, 43008)  [16][512]
//   red [43008, 43072)  [16][4]
//   xs  [43072, 47232)  [16][260]  (phase A only)
// ---------------------------------------------------------------------------
__global__ __launch_bounds__(1024, 1) void fused_kernel(
    const float* __restrict__ x, const float* __restrict__ adj,
    const float* __restrict__ W, const float* __restrict__ lw,
    float* __restrict__ out) {
    extern __shared__ float sm[];
    float* sj   = sm;
    ull*   si2  = (ull*)(sm + 32768);
    float* adjs = sm + 34816;
    float* red  = sm + 43008;
    float* xs   = sm + 43072;
    float* Wl   = sm;                 // phase A overlay

    int bid = blockIdx.x;
    int b = bid >> 5, i0 = (bid & 31) << 4;
    int tid = threadIdx.x;

    // ---- adj tile prefetch (independent of everything) ---------------------
    {
        const float4* asrc = (const float4*)(adj + (size_t)(b * Nv + i0) * Nv);
        float4* adst = (float4*)adjs;
        adst[tid]        = asrc[tid];
        adst[tid + 1024] = asrc[tid + 1024];
    }

    // ---- Phase A staging ----------------------------------------------------
    {
        int r = tid >> 6, d4 = tid & 63;           // 1024 = 16*64
        *(float4*)&xs[r * 260 + d4 * 4] =
            *(const float4*)&x[(size_t)(b * Nv + i0 + r) * Dv + d4 * 4];
    }
#pragma unroll
    for (int k = 0; k < 4; ++k)
        ((float4*)Wl)[tid + k * 1024] = ((const float4*)W)[tid + k * 1024];
    __syncthreads();

    // ---- Phase A compute: one (r,l) output per thread -----------------------
    {
        int r = tid & 15, l = tid >> 4;
        const float* xp = xs + r * 260;
        const float* wp = Wl + l * 256;
        float acc0 = 0.f, acc1 = 0.f;
#pragma unroll 8
        for (int d4 = 0; d4 < 64; ++d4) {
            float4 xv = *(const float4*)&xp[d4 * 4];
            float4 wv = *(const float4*)&wp[d4 * 4];
            acc0 = fmaf(xv.x, wv.x, acc0);
            acc1 = fmaf(xv.y, wv.y, acc1);
            acc0 = fmaf(xv.z, wv.z, acc0);
            acc1 = fmaf(xv.w, wv.w, acc1);
        }
        float a = (acc0 + acc1) * lw[l];
        g_xh[b * (Lv * Nv) + l * Nv + i0 + r] = a;
        si2[l * 16 + r] = pk2(-a);
    }

    // ---- Device-wide barrier ------------------------------------------------
    __syncthreads();
    if (tid == 0) {
        __threadfence();
        unsigned snap = *(volatile unsigned*)&g_release;
        unsigned old  = atomicAdd(&g_count, 1);
        if (old == 127u) {
            g_count = 0;
            __threadfence();
            atomicAdd(&g_release, 1);
        } else {
            while (*(volatile unsigned*)&g_release == snap) __nanosleep(32);
        }
        __threadfence();
    }
    __syncthreads();

    // ---- stage sj (overwrites Wl, dead) -------------------------------------
    const float* xh = g_xh + b * (Lv * Nv);
#pragma unroll
    for (int k = 0; k < 8; ++k)
        ((float4*)sj)[tid + k * 1024] = ((const float4*)xh)[tid + k * 1024];
    __syncthreads();

    // ---- mainloop: 2 rows x 4 j x FULL 64 l per warp ------------------------
    int w    = tid >> 5;
    int lane = tid & 31;
    int rg = w & 7;            // rows 2rg, 2rg+1
    int jq = w >> 3;           // j quarter
    int jbase = jq * 128 + lane * 4;

    const ull ABS2 = 0x7FFFFFFF7FFFFFFFull;
    ull a00 = 0, a01 = 0, a10 = 0, a11 = 0;

    const float* sjp = sj + jbase;
    const ull*   sip = si2 + rg * 2;

#pragma unroll 16
    for (int l = 0; l < 64; ++l) {
        ulonglong2 j01 = *(const ulonglong2*)(sjp + (size_t)l * Nv);
        ulonglong2 nn  = *(const ulonglong2*)(sip + l * 16);
        a00 = add2(a00, add2(j01.x, nn.x) & ABS2);
        a01 = add2(a01, add2(j01.y, nn.x) & ABS2);
        a10 = add2(a10, add2(j01.x, nn.y) & ABS2);
        a11 = add2(a11, add2(j01.y, nn.y) & ABS2);
    }

    // ---- epilogue: 2 rows per warp, warp-local sums -------------------------
    int r0 = rg * 2, r1 = r0 + 1;
    float e0[4], e1[4];
    {
        float v;
        float4 A0 = *(const float4*)&adjs[r0 * Nv + jbase];
        v = lo2(a00); v = v > 0.f ? v : 0.01f * v; e0[0] = A0.x * __expf(v);
        v = hi2(a00); v = v > 0.f ? v : 0.01f * v; e0[1] = A0.y * __expf(v);
        v = lo2(a01); v = v > 0.f ? v : 0.01f * v; e0[2] = A0.z * __expf(v);
        v = hi2(a01); v = v > 0.f ? v : 0.01f * v; e0[3] = A0.w * __expf(v);
        float4 A1 = *(const float4*)&adjs[r1 * Nv + jbase];
        v = lo2(a10); v = v > 0.f ? v : 0.01f * v; e1[0] = A1.x * __expf(v);
        v = hi2(a10); v = v > 0.f ? v : 0.01f * v; e1[1] = A1.y * __expf(v);
        v = lo2(a11); v = v > 0.f ? v : 0.01f * v; e1[2] = A1.z * __expf(v);
        v = hi2(a11); v = v > 0.f ? v : 0.01f * v; e1[3] = A1.w * __expf(v);

        float s0 = e0[0] + e0[1] + e0[2] + e0[3];
        float s1 = e1[0] + e1[1] + e1[2] + e1[3];
#pragma unroll
        for (int o = 16; o; o >>= 1) {
            s0 += __shfl_xor_sync(0xffffffffu, s0, o);
            s1 += __shfl_xor_sync(0xffffffffu, s1, o);
        }
        if (lane == 0) {
            red[r0 * 4 + jq] = s0;
            red[r1 * 4 + jq] = s1;
        }
    }
    __syncthreads();

    // ---- normalize + store --------------------------------------------------
    {
        float4 s40 = *(const float4*)&red[r0 * 4];
        float4 s41 = *(const float4*)&red[r1 * 4];
        float rs0 = 1.0f / (s40.x + s40.y + s40.z + s40.w);
        float rs1 = 1.0f / (s41.x + s41.y + s41.z + s41.w);
        float4 o4;
        o4.x = e0[0] * rs0 + 1e-10f;
        o4.y = e0[1] * rs0 + 1e-10f;
        o4.z = e0[2] * rs0 + 1e-10f;
        o4.w = e0[3] * rs0 + 1e-10f;
        *(float4*)&out[(size_t)(b * Nv + i0 + r0) * Nv + jbase] = o4;
        o4.x = e1[0] * rs1 + 1e-10f;
        o4.y = e1[1] * rs1 + 1e-10f;
        o4.z = e1[2] * rs1 + 1e-10f;
        o4.w = e1[3] * rs1 + 1e-10f;
        *(float4*)&out[(size_t)(b * Nv + i0 + r1) * Nv + jbase] = o4;
    }
}

extern "C" void kernel_launch(void* const* d_in, const int* in_sizes, int n_in,
                              void* d_out, int out_size) {
    (void)in_sizes; (void)n_in; (void)out_size;
    const float* x   = (const float*)d_in[0];
    const float* adj = (const float*)d_in[1];
    const float* W   = (const float*)d_in[2];
    const float* lw  = (const float*)d_in[3];
    float* out = (float*)d_out;

    const int smem = 47232 * 4;   // 188928 B
    cudaFuncSetAttribute(fused_kernel,
                         cudaFuncAttributeMaxDynamicSharedMemorySize, smem);
    cudaFuncSetAttribute(fused_kernel,
                         cudaFuncAttributePreferredSharedMemoryCarveout,
                         cudaSharedmemCarveoutMaxShared);

    fused_kernel<<<Bv * 32, 1024, smem>>>(x, adj, W, lw, out);
}